// round 11
// baseline (speedup 1.0000x reference)
#include <cuda_runtime.h>
#include <cuda_bf16.h>

#define TABLE_SCALE 1024.0f   // 2^10
#define TABLE_SIZE  4096
#define TABLE_MAX   (TABLE_SIZE - 1)
#define UNROLL 4
#define THREADS 256
#define CHUNK_F4 (THREADS * UNROLL)    // 1024 float4 = 16 KB tile
#define NUM_CTAS (152 * 8)             // one resident wave on GB300

__device__ unsigned int g_ticket;

__device__ __forceinline__ int table_idx(float x) {
    int c = (int)(fabsf(x) * TABLE_SCALE);   // truncation toward zero
    return min(c, TABLE_MAX);
}

__global__ void SecGELU_init(unsigned int start) {
    g_ticket = start;
}

// R9 winner (U=4 front-batched .cs loads, smem table gathers, .cs stores)
// + persistent CTAs with a LATENCY-HIDDEN work-stealing ticket: the next
// chunk's atomicAdd is issued at loop top, overlapping its ~318-cycle
// latency with the current chunk's ~8700 cycles of streaming work. This
// removes the 13.47-wave quantization tail + cross-CTA spread of the flat
// grid (R4's version regressed only because its atomic sat exposed between
// chunks). Table is filled once per CTA (1216×) instead of 16384×.
__global__ void __launch_bounds__(THREADS) SecGELU_kernel(
    const float4* __restrict__ x,
    const float* __restrict__ table,
    float4* __restrict__ out,
    int n4, unsigned int num_chunks)
{
    __shared__ float table_s[TABLE_SIZE];
    __shared__ unsigned int s_next;

    {   // cooperative fill: 4096 floats = 1024 float4, 4 per thread
        const float4* t4 = (const float4*)table;
        float4* s4 = (float4*)table_s;
        #pragma unroll
        for (int k = 0; k < TABLE_SIZE / 4 / THREADS; k++)
            s4[threadIdx.x + k * THREADS] = t4[threadIdx.x + k * THREADS];
    }
    __syncthreads();

    unsigned int chunk = blockIdx.x;

    while (chunk < num_chunks) {
        // Prefetch next ticket NOW; latency hides under the chunk below.
        if (threadIdx.x == 0)
            s_next = atomicAdd(&g_ticket, 1u);

        int base = (int)(chunk * CHUNK_F4) + threadIdx.x;

        if (base + (UNROLL - 1) * THREADS < n4) {
            float4 v[UNROLL];
            #pragma unroll
            for (int k = 0; k < UNROLL; k++)
                v[k] = __ldcs(x + base + k * THREADS);   // front-batched

            float t[UNROLL][4];
            #pragma unroll
            for (int k = 0; k < UNROLL; k++) {
                t[k][0] = table_s[table_idx(v[k].x)];
                t[k][1] = table_s[table_idx(v[k].y)];
                t[k][2] = table_s[table_idx(v[k].z)];
                t[k][3] = table_s[table_idx(v[k].w)];
            }

            #pragma unroll
            for (int k = 0; k < UNROLL; k++) {
                float4 r;
                r.x = (v[k].x >= 0.0f ? v[k].x : 0.0f) - t[k][0];
                r.y = (v[k].y >= 0.0f ? v[k].y : 0.0f) - t[k][1];
                r.z = (v[k].z >= 0.0f ? v[k].z : 0.0f) - t[k][2];
                r.w = (v[k].w >= 0.0f ? v[k].w : 0.0f) - t[k][3];
                __stcs(out + base + k * THREADS, r);
            }
        } else {
            #pragma unroll
            for (int k = 0; k < UNROLL; k++) {
                int i = base + k * THREADS;
                if (i < n4) {
                    float4 v = __ldcs(x + i);
                    float4 r;
                    r.x = (v.x >= 0.0f ? v.x : 0.0f) - table_s[table_idx(v.x)];
                    r.y = (v.y >= 0.0f ? v.y : 0.0f) - table_s[table_idx(v.y)];
                    r.z = (v.z >= 0.0f ? v.z : 0.0f) - table_s[table_idx(v.z)];
                    r.w = (v.w >= 0.0f ? v.w : 0.0f) - table_s[table_idx(v.w)];
                    __stcs(out + i, r);
                }
            }
        }

        __syncthreads();          // s_next written + all threads done with chunk
        chunk = s_next;
        __syncthreads();          // all read s_next before tid0 rewrites it
    }
}

// Tail handler for n not divisible by 4 (not needed for 2^26, but safe).
__global__ void SecGELU_tail(
    const float* __restrict__ x,
    const float* __restrict__ table,
    float* __restrict__ out,
    int start, int n)
{
    int i = start + blockIdx.x * blockDim.x + threadIdx.x;
    if (i >= n) return;
    float v = x[i];
    out[i] = (v >= 0.0f ? v : 0.0f) - __ldg(table + table_idx(v));
}

extern "C" void kernel_launch(void* const* d_in, const int* in_sizes, int n_in,
                              void* d_out, int out_size) {
    const float* x     = (const float*)d_in[0];
    const float* table = (const float*)d_in[1];
    float* out = (float*)d_out;

    int n  = in_sizes[0];
    int n4 = n >> 2;

    if (n4 > 0) {
        unsigned int num_chunks = (unsigned int)((n4 + CHUNK_F4 - 1) / CHUNK_F4);
        unsigned int ctas = num_chunks < NUM_CTAS ? num_chunks : NUM_CTAS;

        SecGELU_init<<<1, 1>>>(ctas);   // ticket starts past pre-assigned chunks
        SecGELU_kernel<<<ctas, THREADS>>>(
            (const float4*)x, table, (float4*)out, n4, num_chunks);
    }
    int rem = n - (n4 << 2);
    if (rem > 0) {
        SecGELU_tail<<<1, 32>>>(x, table, out, n4 << 2, n);
    }
}